// round 15
// baseline (speedup 1.0000x reference)
#include <cuda_runtime.h>
#include <cuda_bf16.h>
#include <math.h>
#include <stdint.h>

#define BB 16
#define SEQ 197
#define NROWS (BB*SEQ)        // 3152
#define DIMM 256
#define DI 512
#define DS 16
#define PD 768
#define NPATCH 196
#define PROWS (BB*NPATCH)     // 3136
#define NCLS 1000
#define NL 8

// ---------------- scratch (device globals; no allocation allowed) -------------
__device__ __align__(256) __nv_bfloat16 g_xpb[PROWS*PD];
__device__ __align__(256) float g_xe [PROWS*DIMM];
__device__ __align__(256) float g_res[NROWS*DIMM];
__device__ __align__(256) __nv_bfloat16 g_xnb[NROWS*DIMM];
__device__ __align__(256) __nv_bfloat16 g_xzb[NROWS*2*DI];   // in-proj out (bf16)
__device__ __align__(256) __nv_bfloat16 g_ub [NROWS*DI];     // conv out bf16 (GEMM A)
__device__ __align__(256) float g_uf [NROWS*DI];             // conv out fp32 (scan)
__device__ __align__(256) float g_dbc[NROWS*48];
__device__ __align__(256) __nv_bfloat16 g_yb [NROWS*DI];

// bf16 weights (converted per launch)
__device__ __align__(256) __nv_bfloat16 w_pe [PD*DIMM];
__device__ __align__(256) __nv_bfloat16 w_in [NL*DIMM*2*DI];
__device__ __align__(256) __nv_bfloat16 w_xp [NL*DI*48];
__device__ __align__(256) __nv_bfloat16 w_out[NL*DI*DIMM];

// ---------------- fast math helpers -------------------------------------------
__device__ __forceinline__ float fex2(float x){ float y; asm("ex2.approx.ftz.f32 %0,%1;":"=f"(y):"f"(x)); return y; }
__device__ __forceinline__ float flg2(float x){ float y; asm("lg2.approx.ftz.f32 %0,%1;":"=f"(y):"f"(x)); return y; }
__device__ __forceinline__ float frcp(float x){ float y; asm("rcp.approx.ftz.f32 %0,%1;":"=f"(y):"f"(x)); return y; }
#define LOG2E 1.4426950408889634f
#define LN2   0.6931471805599453f
__device__ __forceinline__ float siluf(float x){ return x * frcp(1.f + fex2(-x * LOG2E)); }
__device__ __forceinline__ float softplusf(float x){
    return (x > 20.f) ? x : LN2 * flg2(1.f + fex2(x * LOG2E));
}

__device__ __forceinline__ float blockReduce256(float v, float* red) {
    int lane = threadIdx.x & 31, w = threadIdx.x >> 5;
    #pragma unroll
    for (int o = 16; o; o >>= 1) v += __shfl_xor_sync(0xffffffffu, v, o);
    __syncthreads();
    if (lane == 0) red[w] = v;
    __syncthreads();
    float t = 0.f;
    if (w == 0) {
        t = (lane < 8) ? red[lane] : 0.f;
        #pragma unroll
        for (int o = 4; o; o >>= 1) t += __shfl_xor_sync(0xffffffffu, t, o);
        if (lane == 0) red[0] = t;
    }
    __syncthreads();
    float r = red[0];
    __syncthreads();
    return r;
}

// ---------------- merged weight convert ----------------------------------------
__global__ void cvt_all(const float* __restrict__ pe, const float* __restrict__ inw,
                        const float* __restrict__ xp, const float* __restrict__ ow,
                        __nv_bfloat16* ope, __nv_bfloat16* oin,
                        __nv_bfloat16* oxp, __nv_bfloat16* oow)
{
    int i = blockIdx.x * 256 + threadIdx.x;
    const int c0 = PD*DIMM/4, c1 = NL*DIMM*2*DI/4, c2 = NL*DI*48/4, c3 = NL*DI*DIMM/4;
    const float* src; __nv_bfloat16* dst;
    if (i < c0) { src = pe; dst = ope; }
    else if ((i -= c0) < c1) { src = inw; dst = oin; }
    else if ((i -= c1) < c2) { src = xp; dst = oxp; }
    else if ((i -= c2) < c3) { src = ow; dst = oow; }
    else return;
    float4 v = ((const float4*)src)[i];
    ((__nv_bfloat162*)dst)[2*i]   = __floats2bfloat162_rn(v.x, v.y);
    ((__nv_bfloat162*)dst)[2*i+1] = __floats2bfloat162_rn(v.z, v.w);
}

// ---------------- bf16 tensor-core GEMM (cp.async 2-stage + ldmatrix) ----------
__device__ __forceinline__ void ldsm_x4(uint32_t a[4], uint32_t addr){
    asm volatile("ldmatrix.sync.aligned.m8n8.x4.shared.b16 {%0,%1,%2,%3}, [%4];"
        : "=r"(a[0]),"=r"(a[1]),"=r"(a[2]),"=r"(a[3]) : "r"(addr));
}
__device__ __forceinline__ void ldsm_x2t(uint32_t b[2], uint32_t addr){
    asm volatile("ldmatrix.sync.aligned.m8n8.x2.trans.shared.b16 {%0,%1}, [%2];"
        : "=r"(b[0]),"=r"(b[1]) : "r"(addr));
}
__device__ __forceinline__ void mma_bf16(float c[4], const uint32_t a[4], const uint32_t b[2]){
    asm volatile(
        "mma.sync.aligned.m16n8k16.row.col.f32.bf16.bf16.f32 "
        "{%0,%1,%2,%3},{%4,%5,%6,%7},{%8,%9},{%0,%1,%2,%3};\n"
        : "+f"(c[0]), "+f"(c[1]), "+f"(c[2]), "+f"(c[3])
        : "r"(a[0]), "r"(a[1]), "r"(a[2]), "r"(a[3]), "r"(b[0]), "r"(b[1]));
}
__device__ __forceinline__ void cp16(uint32_t dst, const void* src, int srcbytes){
    asm volatile("cp.async.cg.shared.global [%0], [%1], 16, %2;\n"
        :: "r"(dst), "l"(src), "r"(srcbytes));
}

// ADD=true: C += result (fp32 only). OT selects output type when ADD=false.
template<int BM, int BN, int WM, int WN, bool ADD, typename OT>
__global__ void __launch_bounds__((BM/WM)*(BN/WN)*32)
mmabf16(const __nv_bfloat16* __restrict__ A, const __nv_bfloat16* __restrict__ B,
        OT* __restrict__ C, int M, int N, int K)
{
    constexpr int WARPS_M = BM/WM, WARPS_N = BN/WN;
    constexpr int NTHR = WARPS_M*WARPS_N*32;
    constexpr int MI = WM/16, NI = WN/8;
    constexpr int ABYTES = BM*128;
    constexpr int BBYTES = 64*BN*2;
    constexpr int BUF = ABYTES + BBYTES;
    constexpr int A_OPS = BM*8/NTHR;
    constexpr int BN8 = BN/8;
    constexpr int B_OPS = 64*BN8/NTHR;

    extern __shared__ char smc[];
    uint32_t smBase;
    asm("{.reg .u64 t; cvta.to.shared.u64 t, %1; cvt.u32.u64 %0, t;}" : "=r"(smBase) : "l"(smc));

    const int tid = threadIdx.x;
    const int lane = tid & 31, warp = tid >> 5;
    const int g = lane >> 2, tin = lane & 3;
    const int wm = warp % WARPS_M, wn = warp / WARPS_M;
    const int m_base = wm*WM, n_base = wn*WN;
    const int m0 = blockIdx.y * BM, n0 = blockIdx.x * BN;

    float acc[MI][NI][4];
    #pragma unroll
    for (int i = 0; i < MI; i++)
        #pragma unroll
        for (int j = 0; j < NI; j++)
            #pragma unroll
            for (int t = 0; t < 4; t++) acc[i][j][t] = 0.f;

    auto stage = [&](int kc, int buf) {
        #pragma unroll
        for (int i = 0; i < A_OPS; i++) {
            int idx = tid + i*NTHR;
            int m = idx >> 3, c = idx & 7;
            int gm = m0 + m;
            int sz = (gm < M) ? 16 : 0;
            int gmc = (gm < M) ? gm : (M-1);
            uint32_t dst = smBase + buf*BUF + m*128 + ((c ^ (m & 7)) << 4);
            cp16(dst, A + (size_t)gmc*K + kc*64 + c*8, sz);
        }
        #pragma unroll
        for (int i = 0; i < B_OPS; i++) {
            int idx = tid + i*NTHR;
            int nc = idx % BN8, k = idx / BN8;
            int gn = n0 + nc*8;
            int sz = (gn < N) ? 16 : 0;
            int gnc = (gn < N) ? gn : 0;
            uint32_t dst = smBase + buf*BUF + ABYTES + k*(BN*2) + ((nc ^ (k & 7)) << 4);
            cp16(dst, B + (size_t)(kc*64 + k)*N + gnc, sz);
        }
        asm volatile("cp.async.commit_group;\n");
    };

    auto compute = [&](int buf) {
        const uint32_t aBuf = smBase + buf*BUF;
        const uint32_t bBuf = aBuf + ABYTES;
        const int sub = lane >> 3, r = lane & 7;
        const int mloc = m_base + (sub & 1)*8 + r;
        const int khalf = sub >> 1;
        const int msw = mloc & 7;
        const int kloc = lane & 15;
        const int nb = n_base >> 3;
        #pragma unroll
        for (int ks = 0; ks < 4; ks++) {
            uint32_t af[MI][4], bf[NI][2];
            #pragma unroll
            for (int mi = 0; mi < MI; mi++) {
                uint32_t addr = aBuf + (mloc + mi*16)*128 + (((ks*2 + khalf) ^ msw) << 4);
                ldsm_x4(af[mi], addr);
            }
            #pragma unroll
            for (int ni = 0; ni < NI; ni++) {
                int k = ks*16 + kloc;
                uint32_t addr = bBuf + k*(BN*2) + (((nb + ni) ^ (kloc & 7)) << 4);
                ldsm_x2t(bf[ni], addr);
            }
            #pragma unroll
            for (int mi = 0; mi < MI; mi++)
                #pragma unroll
                for (int ni = 0; ni < NI; ni++)
                    mma_bf16(acc[mi][ni], af[mi], bf[ni]);
        }
    };

    const int ntile = K / 64;
    stage(0, 0);
    if (ntile > 1) stage(1, 1);
    for (int kc = 0; kc < ntile; kc++) {
        if (kc + 1 < ntile) asm volatile("cp.async.wait_group 1;\n");
        else                asm volatile("cp.async.wait_group 0;\n");
        __syncthreads();
        compute(kc & 1);
        __syncthreads();
        if (kc + 2 < ntile) stage(kc + 2, kc & 1);
    }

    #pragma unroll
    for (int mi = 0; mi < MI; mi++) {
        int gr0 = m0 + m_base + mi*16 + g;
        int gr1 = gr0 + 8;
        #pragma unroll
        for (int ni = 0; ni < NI; ni++) {
            int gc = n0 + n_base + ni*8 + tin*2;
            if (gc < N) {
                if constexpr (sizeof(OT) == 4) {
                    if (gr0 < M) {
                        float2* p = (float2*)(C + (size_t)gr0*N + gc);
                        float2 o = make_float2(acc[mi][ni][0], acc[mi][ni][1]);
                        if constexpr (ADD) { float2 e = *p; o.x += e.x; o.y += e.y; }
                        *p = o;
                    }
                    if (gr1 < M) {
                        float2* p = (float2*)(C + (size_t)gr1*N + gc);
                        float2 o = make_float2(acc[mi][ni][2], acc[mi][ni][3]);
                        if constexpr (ADD) { float2 e = *p; o.x += e.x; o.y += e.y; }
                        *p = o;
                    }
                } else {
                    if (gr0 < M) *(__nv_bfloat162*)(C + (size_t)gr0*N + gc) =
                        __floats2bfloat162_rn(acc[mi][ni][0], acc[mi][ni][1]);
                    if (gr1 < M) *(__nv_bfloat162*)(C + (size_t)gr1*N + gc) =
                        __floats2bfloat162_rn(acc[mi][ni][2], acc[mi][ni][3]);
                }
            }
        }
    }
}

// ---------------- patchify + LN1 (writes bf16) ----------------------------------
__global__ void patchify_ln(const float* __restrict__ img,
                            const float* __restrict__ gg, const float* __restrict__ bb)
{
    __shared__ float sv[PD];
    __shared__ float red[8];
    int r = blockIdx.x;
    int b = r / NPATCH, p = r % NPATCH;
    int hh = p / 14, ww = p % 14;
    int tid = threadIdx.x;
    float lsum = 0.f;
    #pragma unroll
    for (int e = tid; e < PD; e += 256) {
        int c = e % 3, t = e / 3, p2 = t % 16, p1 = t / 16;
        float v = img[(((size_t)(b * 3 + c) * 224 + hh * 16 + p1) * 224) + ww * 16 + p2];
        sv[e] = v; lsum += v;
    }
    float mu = blockReduce256(lsum, red) * (1.f / PD);
    float lq = 0.f;
    #pragma unroll
    for (int e = tid; e < PD; e += 256) { float d = sv[e] - mu; lq += d * d; }
    float var = blockReduce256(lq, red) * (1.f / PD);
    float rs = rsqrtf(var + 1e-5f);
    #pragma unroll
    for (int e = tid; e < PD; e += 256)
        g_xpb[(size_t)r * PD + e] = __float2bfloat16((sv[e] - mu) * rs * gg[e] + bb[e]);
}

// ---------------- bias + LN2 + pos_emb + cls token (warp per row) --------------
// writes the initial residual into g_res
__global__ void pe2_posemb(const float* __restrict__ pe_b,
                           const float* __restrict__ g2, const float* __restrict__ b2,
                           const float* __restrict__ pos, const float* __restrict__ cls)
{
    int row = blockIdx.x * 8 + (threadIdx.x >> 5);
    int lane = threadIdx.x & 31;
    if (row < PROWS) {
        int b = row / NPATCH, p = row % NPATCH;
        const float4* xe4 = (const float4*)(g_xe + (size_t)row * DIMM);
        const float4* pb4 = (const float4*)pe_b;
        float4 v[2]; float s = 0.f;
        #pragma unroll
        for (int j = 0; j < 2; j++) {
            float4 t = xe4[lane + j*32], pb = pb4[lane + j*32];
            t.x += pb.x; t.y += pb.y; t.z += pb.z; t.w += pb.w;
            v[j] = t; s += t.x + t.y + t.z + t.w;
        }
        #pragma unroll
        for (int o = 16; o; o >>= 1) s += __shfl_xor_sync(0xffffffffu, s, o);
        float mu = s * (1.f / DIMM);
        float q = 0.f;
        #pragma unroll
        for (int j = 0; j < 2; j++) {
            float4 t = v[j];
            q += (t.x-mu)*(t.x-mu) + (t.y-mu)*(t.y-mu) + (t.z-mu)*(t.z-mu) + (t.w-mu)*(t.w-mu);
        }
        #pragma unroll
        for (int o = 16; o; o >>= 1) q += __shfl_xor_sync(0xffffffffu, q, o);
        float rs = rsqrtf(q * (1.f / DIMM) + 1e-5f);
        const float4* g4 = (const float4*)g2;
        const float4* bb4 = (const float4*)b2;
        const float4* pos4 = (const float4*)(pos + (size_t)(1 + p) * DIMM);
        float4* xo = (float4*)(g_res + ((size_t)(b * SEQ + 1 + p)) * DIMM);
        #pragma unroll
        for (int j = 0; j < 2; j++) {
            float4 t = v[j], w4 = g4[lane + j*32], bv = bb4[lane + j*32], pv = pos4[lane + j*32];
            float4 o4;
            o4.x = (t.x - mu) * rs * w4.x + bv.x + pv.x;
            o4.y = (t.y - mu) * rs * w4.y + bv.y + pv.y;
            o4.z = (t.z - mu) * rs * w4.z + bv.z + pv.z;
            o4.w = (t.w - mu) * rs * w4.w + bv.w + pv.w;
            xo[lane + j*32] = o4;
        }
    } else if (row < PROWS + BB) {
        int b = row - PROWS;
        const float4* c4 = (const float4*)cls;
        const float4* pos4 = (const float4*)pos;
        float4* xo = (float4*)(g_res + ((size_t)(b * SEQ)) * DIMM);
        #pragma unroll
        for (int j = 0; j < 2; j++) {
            float4 cv = c4[lane + j*32], pv = pos4[lane + j*32];
            xo[lane + j*32] = make_float4(cv.x+pv.x, cv.y+pv.y, cv.z+pv.z, cv.w+pv.w);
        }
    }
}

// ---------------- LN of residual (warp/row, float4 in, bf16 out) ----------------
__global__ void ln_res(const float* __restrict__ lw, const float* __restrict__ lb)
{
    int row = blockIdx.x * 8 + (threadIdx.x >> 5);
    int lane = threadIdx.x & 31;
    const float4* rr = (const float4*)(g_res + (size_t)row * DIMM);
    float4 v[2]; float s = 0.f;
    #pragma unroll
    for (int j = 0; j < 2; j++) {
        float4 t = rr[lane + j * 32];
        v[j] = t;
        s += t.x + t.y + t.z + t.w;
    }
    #pragma unroll
    for (int o = 16; o; o >>= 1) s += __shfl_xor_sync(0xffffffffu, s, o);
    float mu = s * (1.f / DIMM);
    float q = 0.f;
    #pragma unroll
    for (int j = 0; j < 2; j++) {
        float4 t = v[j];
        q += (t.x-mu)*(t.x-mu) + (t.y-mu)*(t.y-mu) + (t.z-mu)*(t.z-mu) + (t.w-mu)*(t.w-mu);
    }
    #pragma unroll
    for (int o = 16; o; o >>= 1) q += __shfl_xor_sync(0xffffffffu, q, o);
    float rs = rsqrtf(q * (1.f / DIMM) + 1e-5f);
    const float4* lw4 = (const float4*)lw;
    const float4* lb4 = (const float4*)lb;
    __nv_bfloat162* xo = (__nv_bfloat162*)(g_xnb + (size_t)row * DIMM);
    #pragma unroll
    for (int j = 0; j < 2; j++) {
        float4 t = v[j], w4 = lw4[lane + j*32], b4 = lb4[lane + j*32];
        float ox = (t.x - mu) * rs * w4.x + b4.x;
        float oy = (t.y - mu) * rs * w4.y + b4.y;
        float oz = (t.z - mu) * rs * w4.z + b4.z;
        float ow = (t.w - mu) * rs * w4.w + b4.w;
        xo[(lane + j*32)*2]     = __floats2bfloat162_rn(ox, oy);
        xo[(lane + j*32)*2 + 1] = __floats2bfloat162_rn(oz, ow);
    }
}

// ---------------- depthwise causal conv (k=4) + silu, 8 ch/thread, 16B taps ----
__global__ void conv_silu(const float* __restrict__ cw, const float* __restrict__ cb)
{
    int i = blockIdx.x * 256 + threadIdx.x;
    if (i >= NROWS * DI / 8) return;
    int d8 = (i & 63) * 8;              // DI/8 == 64 groups per row
    int row = i >> 6;
    int l = row % SEQ; int b = row / SEQ;

    float acc[8];
    {
        float4 cb0 = *(const float4*)(cb + d8);
        float4 cb1 = *(const float4*)(cb + d8 + 4);
        acc[0]=cb0.x; acc[1]=cb0.y; acc[2]=cb0.z; acc[3]=cb0.w;
        acc[4]=cb1.x; acc[5]=cb1.y; acc[6]=cb1.z; acc[7]=cb1.w;
    }
    float4 w[8];
    #pragma unroll
    for (int j = 0; j < 8; j++) w[j] = *(const float4*)(cw + (d8 + j) * 4);

    #pragma unroll
    for (int k = 0; k < 4; k++) {
        int ll = l - 3 + k;
        if (ll >= 0) {
            uint4 xv = *(const uint4*)(g_xzb + (size_t)(b * SEQ + ll) * (2*DI) + d8);
            const __nv_bfloat162* bp = (const __nv_bfloat162*)&xv;   // 4 pairs = ch 0..7
            #pragma unroll
            for (int j2 = 0; j2 < 4; j2++) {
                float2 f = __bfloat1622float2(bp[j2]);
                acc[j2*2]   = fmaf(f.x, ((const float*)&w[j2*2  ])[k], acc[j2*2]);
                acc[j2*2+1] = fmaf(f.y, ((const float*)&w[j2*2+1])[k], acc[j2*2+1]);
            }
        }
    }
    // fp32 out for scan (2x16B) + bf16 out for GEMM (16B)
    float4 o0 = make_float4(siluf(acc[0]), siluf(acc[1]), siluf(acc[2]), siluf(acc[3]));
    float4 o1 = make_float4(siluf(acc[4]), siluf(acc[5]), siluf(acc[6]), siluf(acc[7]));
    *(float4*)(g_uf + (size_t)row * DI + d8)     = o0;
    *(float4*)(g_uf + (size_t)row * DI + d8 + 4) = o1;
    uint4 ov;
    __nv_bfloat162* op = (__nv_bfloat162*)&ov;
    op[0] = __floats2bfloat162_rn(o0.x, o0.y);
    op[1] = __floats2bfloat162_rn(o0.z, o0.w);
    op[2] = __floats2bfloat162_rn(o1.x, o1.y);
    op[3] = __floats2bfloat162_rn(o1.z, o1.w);
    *(uint4*)(g_ub + (size_t)row * DI + d8) = ov;
}

// ---------------- selective scan: full cp.async staging (dbc + u + z[bf16]) -----
__global__ void scan_k(const float* __restrict__ A_log, const float* __restrict__ Dpv,
                       const float* __restrict__ dtw, const float* __restrict__ dtb)
{
    __shared__ __align__(16) float sdbc[3][4][48];
    __shared__ __align__(16) float su  [3][4][64];
    __shared__ __align__(16) __nv_bfloat16 szb[3][4][64];
    int b = blockIdx.x >> 3;
    int chunk = blockIdx.x & 7;
    int tid = threadIdx.x;
    int d = chunk * 64 + (tid >> 1);
    int dloc = tid >> 1;
    int half = tid & 1;
    int n0 = half * 8;
    int row0 = b * SEQ;

    uint32_t dbcBase, uBase, zBase;
    asm("{.reg .u64 t; cvta.to.shared.u64 t, %1; cvt.u32.u64 %0, t;}" : "=r"(dbcBase) : "l"((void*)sdbc));
    asm("{.reg .u64 t; cvta.to.shared.u64 t, %1; cvt.u32.u64 %0, t;}" : "=r"(uBase) : "l"((void*)su));
    asm("{.reg .u64 t; cvta.to.shared.u64 t, %1; cvt.u32.u64 %0, t;}" : "=r"(zBase) : "l"((void*)szb));

    float A2[8], hst[8];
    #pragma unroll
    for (int j = 0; j < 8; j++) {
        A2[j] = -expf(A_log[(size_t)d * DS + n0 + j]) * LOG2E;
        hst[j] = 0.f;
    }
    float w16[16];
    #pragma unroll
    for (int k = 0; k < 16; k++) w16[k] = dtw[k * DI + d];
    float bias = dtb[d];
    float dpd = Dpv[d];

    const int NG = (SEQ + 3) / 4;
    const int ch0 = chunk * 64;

    // non-blocking staging: dbc 48 + u 64 + z 32 = 144 x 16B chunks per group
    auto stageA = [&](int grp) {
        int buf = grp % 3;
        #pragma unroll
        for (int pass = 0; pass < 2; pass++) {
            int c = tid + pass * 128;
            if (c < 48) {
                int r = c / 12, off = c % 12;
                int l = grp * 4 + r;
                if (l < SEQ) {
                    uint32_t dst = dbcBase + (((buf * 4 + r) * 48) + off * 4) * 4;
                    cp16(dst, g_dbc + (size_t)(row0 + l) * 48 + off * 4, 16);
                }
            } else if (c < 112) {
                int c2 = c - 48;
                int r = c2 / 16, off = c2 % 16;
                int l = grp * 4 + r;
                if (l < SEQ) {
                    uint32_t dst = uBase + (((buf * 4 + r) * 64) + off * 4) * 4;
                    cp16(dst, g_uf + (size_t)(row0 + l) * DI + ch0 + off * 4, 16);
                }
            } else if (c < 144) {
                int c3 = c - 112;
                int r = c3 / 8, off = c3 % 8;     // 8 x 16B = 64 bf16
                int l = grp * 4 + r;
                if (l < SEQ) {
                    uint32_t dst = zBase + (((buf * 4 + r) * 64) + off * 8) * 2;
                    cp16(dst, g_xzb + (size_t)(row0 + l) * (2*DI) + DI + ch0 + off * 8, 16);
                }
            }
        }
        asm volatile("cp.async.commit_group;\n");
    };

    stageA(0);
    if (NG > 1) stageA(1);

    for (int grp = 0; grp < NG; grp++) {
        if (grp + 1 < NG) asm volatile("cp.async.wait_group 1;\n");
        else              asm volatile("cp.async.wait_group 0;\n");
        __syncthreads();
        if (grp + 2 < NG) stageA(grp + 2);
        int buf = grp % 3;
        #pragma unroll
        for (int g2 = 0; g2 < 4; g2++) {
            int l = grp * 4 + g2;
            if (l < SEQ) {
                float uv = su[buf][g2][dloc];
                float acc = bias;
                #pragma unroll
                for (int k = 0; k < 16; k++) acc += sdbc[buf][g2][k] * w16[k];
                float dt = softplusf(acc);
                float xt = dt * uv;
                float y = 0.f;
                #pragma unroll
                for (int j = 0; j < 8; j++) {
                    float dA = fex2(dt * A2[j]);
                    float hv = dA * hst[j] + xt * sdbc[buf][g2][16 + n0 + j];
                    hst[j] = hv;
                    y += hv * sdbc[buf][g2][32 + n0 + j];
                }
                y += __shfl_xor_sync(0xffffffffu, y, 1);
                if (!half) {
                    float zv = __bfloat162float(szb[buf][g2][dloc]);
                    g_yb[(size_t)(row0 + l) * DI + d] =
                        __float2bfloat16((y + uv * dpd) * siluf(zv));
                }
            }
        }
        __syncthreads();
    }
}

// ---------------- final LN on token 0 + head (fused) ----------------------------
__global__ void lnhead_k(const float* __restrict__ gw, const float* __restrict__ gb,
                         const float* __restrict__ hw, const float* __restrict__ hb,
                         float* __restrict__ out)
{
    __shared__ float red[8];
    __shared__ float sx[DIMM];
    int b = blockIdx.x; int c = threadIdx.x;
    size_t idx = (size_t)(b * SEQ) * DIMM + c;
    float v = g_res[idx];
    float mu = blockReduce256(v, red) * (1.f / DIMM);
    float d = v - mu;
    float var = blockReduce256(d * d, red) * (1.f / DIMM);
    sx[c] = d * rsqrtf(var + 1e-5f) * gw[c] + gb[c];
    __syncthreads();
    for (int n = c; n < NCLS; n += 256) {
        float acc = hb[n];
        #pragma unroll 4
        for (int k = 0; k < DIMM; k++) acc += sx[k] * hw[(size_t)k * NCLS + n];
        out[(size_t)b * NCLS + n] = acc;
    }
}

// ---------------- launch ---------------------------------------------------------
extern "C" void kernel_launch(void* const* d_in, const int* in_sizes, int n_in,
                              void* d_out, int out_size)
{
    (void)in_sizes; (void)n_in; (void)out_size;
    const float* img      = (const float*)d_in[0];
    const float* pe_ln1_g = (const float*)d_in[1];
    const float* pe_ln1_b = (const float*)d_in[2];
    const float* pe_w     = (const float*)d_in[3];
    const float* pe_b     = (const float*)d_in[4];
    const float* pe_ln2_g = (const float*)d_in[5];
    const float* pe_ln2_b = (const float*)d_in[6];
    const float* pos_emb  = (const float*)d_in[7];
    const float* cls_tok  = (const float*)d_in[8];
    const float* ln_w     = (const float*)d_in[9];
    const float* ln_b     = (const float*)d_in[10];
    const float* in_w     = (const float*)d_in[11];
    const float* conv_w   = (const float*)d_in[12];
    const float* conv_b   = (const float*)d_in[13];
    const float* xproj_w  = (const float*)d_in[14];
    const float* dtproj_w = (const float*)d_in[15];
    const float* dtproj_b = (const float*)d_in[16];
    const float* A_log    = (const float*)d_in[17];
    const float* Dp       = (const float*)d_in[18];
    const float* out_w    = (const float*)d_in[19];
    const float* normf_w  = (const float*)d_in[20];
    const float* normf_b  = (const float*)d_in[21];
    const float* head_w   = (const float*)d_in[22];
    const float* head_b   = (const float*)d_in[23];
    float* out = (float*)d_out;

    __nv_bfloat16 *p_xpb, *p_xnb, *p_ub, *p_yb, *p_xzb, *p_wpe, *p_win, *p_wxp, *p_wout;
    float *p_xe, *p_res, *p_dbc;
    cudaGetSymbolAddress((void**)&p_xpb, g_xpb);
    cudaGetSymbolAddress((void**)&p_xnb, g_xnb);
    cudaGetSymbolAddress((void**)&p_ub , g_ub );
    cudaGetSymbolAddress((void**)&p_yb , g_yb );
    cudaGetSymbolAddress((void**)&p_xzb, g_xzb);
    cudaGetSymbolAddress((void**)&p_wpe, w_pe );
    cudaGetSymbolAddress((void**)&p_win, w_in );
    cudaGetSymbolAddress((void**)&p_wxp, w_xp );
    cudaGetSymbolAddress((void**)&p_wout, w_out);
    cudaGetSymbolAddress((void**)&p_xe , g_xe );
    cudaGetSymbolAddress((void**)&p_res, g_res);
    cudaGetSymbolAddress((void**)&p_dbc, g_dbc);

    const int SMEM_BIG   = 2 * (128*128 + 64*128*2);   // 65536 (<128,128>)
    const int SMEM_SMALL = 2 * (64*128 + 64*64*2);     // 32768 (<64,64>)
    cudaFuncSetAttribute((const void*)mmabf16<128,128,64,32,false,__nv_bfloat16>,
                         cudaFuncAttributeMaxDynamicSharedMemorySize, SMEM_BIG);
    cudaFuncSetAttribute((const void*)mmabf16<64,64,32,32,false,float>,
                         cudaFuncAttributeMaxDynamicSharedMemorySize, SMEM_SMALL);
    cudaFuncSetAttribute((const void*)mmabf16<64,64,32,32,true,float>,
                         cudaFuncAttributeMaxDynamicSharedMemorySize, SMEM_SMALL);

    // weight conversion (single kernel)
    {
        int total4 = (PD*DIMM + NL*DIMM*2*DI + NL*DI*48 + NL*DI*DIMM) / 4;
        cvt_all<<<(total4 + 255)/256, 256>>>(pe_w, in_w, xproj_w, out_w,
                                             p_wpe, p_win, p_wxp, p_wout);
    }

    // patch embed
    patchify_ln<<<PROWS, 256>>>(img, pe_ln1_g, pe_ln1_b);
    {   // g_xe = g_xpb @ w_pe  (3136 x 256 x 768)
        dim3 grid(DIMM / 64, PROWS / 64);
        mmabf16<64,64,32,32,false,float><<<grid, 128, SMEM_SMALL>>>(p_xpb, p_wpe, p_xe,
                                                                    PROWS, DIMM, PD);
    }
    pe2_posemb<<<(PROWS + BB + 7) / 8, 256>>>(pe_b, pe_ln2_g, pe_ln2_b, pos_emb, cls_tok);

    for (int i = 0; i < 8; i++) {
        ln_res<<<NROWS / 8, 256>>>(ln_w + i * DIMM, ln_b + i * DIMM);
        {   // g_xzb = g_xnb @ w_in[i]  (3152 x 1024 x 256) -> bf16
            dim3 grid((2 * DI) / 128, (NROWS + 127) / 128);
            mmabf16<128,128,64,32,false,__nv_bfloat16><<<grid, 256, SMEM_BIG>>>(
                p_xnb, p_win + (size_t)i * DIMM * 2 * DI, p_xzb,
                NROWS, 2 * DI, DIMM);
        }
        conv_silu<<<(NROWS * DI / 8 + 255) / 256, 256>>>(conv_w + (size_t)i * DI * 4, conv_b + i * DI);
        {   // g_dbc = g_ub @ w_xp[i]  (3152 x 48 x 512)
            dim3 grid(1, (NROWS + 63) / 64);
            mmabf16<64,64,32,32,false,float><<<grid, 128, SMEM_SMALL>>>(
                p_ub, p_wxp + (size_t)i * DI * 48, p_dbc, NROWS, 48, DI);
        }
        scan_k<<<BB * 8, 128>>>(A_log + (size_t)i * DI * DS, Dp + i * DI,
                                dtproj_w + (size_t)i * 16 * DI, dtproj_b + i * DI);
        {   // g_res += g_yb @ w_out[i]  (3152 x 256 x 512), fused residual
            dim3 grid(DIMM / 64, (NROWS + 63) / 64);
            mmabf16<64,64,32,32,true,float><<<grid, 128, SMEM_SMALL>>>(
                p_yb, p_wout + (size_t)i * DI * DIMM, p_res, NROWS, DIMM, DI);
        }
    }

    lnhead_k<<<BB, 256>>>(normf_w, normf_b, head_w, head_b, out);
}

// round 16
// speedup vs baseline: 1.0719x; 1.0719x over previous
#include <cuda_runtime.h>
#include <cuda_bf16.h>
#include <math.h>
#include <stdint.h>

#define BB 16
#define SEQ 197
#define NROWS (BB*SEQ)        // 3152
#define DIMM 256
#define DI 512
#define DS 16
#define PD 768
#define NPATCH 196
#define PROWS (BB*NPATCH)     // 3136
#define NCLS 1000
#define NL 8

// ---------------- scratch (device globals; no allocation allowed) -------------
__device__ __align__(256) __nv_bfloat16 g_xpb[PROWS*PD];
__device__ __align__(256) float g_xe [PROWS*DIMM];
__device__ __align__(256) float g_res[NROWS*DIMM];
__device__ __align__(256) __nv_bfloat16 g_xnb[NROWS*DIMM];
__device__ __align__(256) float g_xz [NROWS*2*DI];
__device__ __align__(256) __nv_bfloat16 g_ub [NROWS*DI];     // conv out bf16 (GEMM A)
__device__ __align__(256) float g_uf [NROWS*DI];             // conv out fp32 (scan)
__device__ __align__(256) float g_dbc[NROWS*48];
__device__ __align__(256) __nv_bfloat16 g_yb [NROWS*DI];

// bf16 weights (converted per launch)
__device__ __align__(256) __nv_bfloat16 w_pe [PD*DIMM];
__device__ __align__(256) __nv_bfloat16 w_in [NL*DIMM*2*DI];
__device__ __align__(256) __nv_bfloat16 w_xp [NL*DI*48];
__device__ __align__(256) __nv_bfloat16 w_out[NL*DI*DIMM];

// ---------------- fast math helpers -------------------------------------------
__device__ __forceinline__ float fex2(float x){ float y; asm("ex2.approx.ftz.f32 %0,%1;":"=f"(y):"f"(x)); return y; }
__device__ __forceinline__ float flg2(float x){ float y; asm("lg2.approx.ftz.f32 %0,%1;":"=f"(y):"f"(x)); return y; }
__device__ __forceinline__ float frcp(float x){ float y; asm("rcp.approx.ftz.f32 %0,%1;":"=f"(y):"f"(x)); return y; }
#define LOG2E 1.4426950408889634f
#define LN2   0.6931471805599453f
__device__ __forceinline__ float siluf(float x){ return x * frcp(1.f + fex2(-x * LOG2E)); }
__device__ __forceinline__ float softplusf(float x){
    return (x > 20.f) ? x : LN2 * flg2(1.f + fex2(x * LOG2E));
}

__device__ __forceinline__ float blockReduce256(float v, float* red) {
    int lane = threadIdx.x & 31, w = threadIdx.x >> 5;
    #pragma unroll
    for (int o = 16; o; o >>= 1) v += __shfl_xor_sync(0xffffffffu, v, o);
    __syncthreads();
    if (lane == 0) red[w] = v;
    __syncthreads();
    float t = 0.f;
    if (w == 0) {
        t = (lane < 8) ? red[lane] : 0.f;
        #pragma unroll
        for (int o = 4; o; o >>= 1) t += __shfl_xor_sync(0xffffffffu, t, o);
        if (lane == 0) red[0] = t;
    }
    __syncthreads();
    float r = red[0];
    __syncthreads();
    return r;
}

// ---------------- merged weight convert ----------------------------------------
__global__ void cvt_all(const float* __restrict__ pe, const float* __restrict__ inw,
                        const float* __restrict__ xp, const float* __restrict__ ow,
                        __nv_bfloat16* ope, __nv_bfloat16* oin,
                        __nv_bfloat16* oxp, __nv_bfloat16* oow)
{
    int i = blockIdx.x * 256 + threadIdx.x;
    const int c0 = PD*DIMM/4, c1 = NL*DIMM*2*DI/4, c2 = NL*DI*48/4, c3 = NL*DI*DIMM/4;
    const float* src; __nv_bfloat16* dst;
    if (i < c0) { src = pe; dst = ope; }
    else if ((i -= c0) < c1) { src = inw; dst = oin; }
    else if ((i -= c1) < c2) { src = xp; dst = oxp; }
    else if ((i -= c2) < c3) { src = ow; dst = oow; }
    else return;
    float4 v = ((const float4*)src)[i];
    ((__nv_bfloat162*)dst)[2*i]   = __floats2bfloat162_rn(v.x, v.y);
    ((__nv_bfloat162*)dst)[2*i+1] = __floats2bfloat162_rn(v.z, v.w);
}

// ---------------- bf16 tensor-core GEMM (cp.async 2-stage + ldmatrix) ----------
__device__ __forceinline__ void ldsm_x4(uint32_t a[4], uint32_t addr){
    asm volatile("ldmatrix.sync.aligned.m8n8.x4.shared.b16 {%0,%1,%2,%3}, [%4];"
        : "=r"(a[0]),"=r"(a[1]),"=r"(a[2]),"=r"(a[3]) : "r"(addr));
}
__device__ __forceinline__ void ldsm_x2t(uint32_t b[2], uint32_t addr){
    asm volatile("ldmatrix.sync.aligned.m8n8.x2.trans.shared.b16 {%0,%1}, [%2];"
        : "=r"(b[0]),"=r"(b[1]) : "r"(addr));
}
__device__ __forceinline__ void mma_bf16(float c[4], const uint32_t a[4], const uint32_t b[2]){
    asm volatile(
        "mma.sync.aligned.m16n8k16.row.col.f32.bf16.bf16.f32 "
        "{%0,%1,%2,%3},{%4,%5,%6,%7},{%8,%9},{%0,%1,%2,%3};\n"
        : "+f"(c[0]), "+f"(c[1]), "+f"(c[2]), "+f"(c[3])
        : "r"(a[0]), "r"(a[1]), "r"(a[2]), "r"(a[3]), "r"(b[0]), "r"(b[1]));
}
__device__ __forceinline__ void cp16(uint32_t dst, const void* src, int srcbytes){
    asm volatile("cp.async.cg.shared.global [%0], [%1], 16, %2;\n"
        :: "r"(dst), "l"(src), "r"(srcbytes));
}

// ADD=true: C += result; the C tile is prefetched into SMEM via cp.async before
// the K-loop (race-free: 1 thread per element).
template<int BM, int BN, int WM, int WN, bool ADD>
__global__ void __launch_bounds__((BM/WM)*(BN/WN)*32)
mmabf16(const __nv_bfloat16* __restrict__ A, const __nv_bfloat16* __restrict__ B,
        float* __restrict__ C, int M, int N, int K)
{
    constexpr int WARPS_M = BM/WM, WARPS_N = BN/WN;
    constexpr int NTHR = WARPS_M*WARPS_N*32;
    constexpr int MI = WM/16, NI = WN/8;
    constexpr int ABYTES = BM*128;
    constexpr int BBYTES = 64*BN*2;
    constexpr int BUF = ABYTES + BBYTES;
    constexpr int A_OPS = BM*8/NTHR;
    constexpr int BN8 = BN/8;
    constexpr int B_OPS = 64*BN8/NTHR;
    constexpr int C_CHUNKS = BM*BN/4;           // 16B chunks of C tile

    extern __shared__ char smc[];
    uint32_t smBase;
    asm("{.reg .u64 t; cvta.to.shared.u64 t, %1; cvt.u32.u64 %0, t;}" : "=r"(smBase) : "l"(smc));
    const uint32_t cBase = smBase + 2*BUF;      // C tile (ADD only)
    float* sC = (float*)(smc + 2*BUF);

    const int tid = threadIdx.x;
    const int lane = tid & 31, warp = tid >> 5;
    const int g = lane >> 2, tin = lane & 3;
    const int wm = warp % WARPS_M, wn = warp / WARPS_M;
    const int m_base = wm*WM, n_base = wn*WN;
    const int m0 = blockIdx.y * BM, n0 = blockIdx.x * BN;

    // prefetch residual C tile (ADD): own commit group, drains under mainloop
    if constexpr (ADD) {
        #pragma unroll
        for (int i = 0; i < C_CHUNKS / NTHR; i++) {
            int idx = tid + i * NTHR;
            int m = idx / (BN/4), c4 = idx % (BN/4);
            int gm = m0 + m;
            int sz = (gm < M) ? 16 : 0;
            int gmc = (gm < M) ? gm : (M-1);
            cp16(cBase + (m * BN + c4*4) * 4, C + (size_t)gmc*N + n0 + c4*4, sz);
        }
        asm volatile("cp.async.commit_group;\n");
    }

    float acc[MI][NI][4];
    #pragma unroll
    for (int i = 0; i < MI; i++)
        #pragma unroll
        for (int j = 0; j < NI; j++)
            #pragma unroll
            for (int t = 0; t < 4; t++) acc[i][j][t] = 0.f;

    auto stage = [&](int kc, int buf) {
        #pragma unroll
        for (int i = 0; i < A_OPS; i++) {
            int idx = tid + i*NTHR;
            int m = idx >> 3, c = idx & 7;
            int gm = m0 + m;
            int sz = (gm < M) ? 16 : 0;
            int gmc = (gm < M) ? gm : (M-1);
            uint32_t dst = smBase + buf*BUF + m*128 + ((c ^ (m & 7)) << 4);
            cp16(dst, A + (size_t)gmc*K + kc*64 + c*8, sz);
        }
        #pragma unroll
        for (int i = 0; i < B_OPS; i++) {
            int idx = tid + i*NTHR;
            int nc = idx % BN8, k = idx / BN8;
            int gn = n0 + nc*8;
            int sz = (gn < N) ? 16 : 0;
            int gnc = (gn < N) ? gn : 0;
            uint32_t dst = smBase + buf*BUF + ABYTES + k*(BN*2) + ((nc ^ (k & 7)) << 4);
            cp16(dst, B + (size_t)(kc*64 + k)*N + gnc, sz);
        }
        asm volatile("cp.async.commit_group;\n");
    };

    auto compute = [&](int buf) {
        const uint32_t aBuf = smBase + buf*BUF;
        const uint32_t bBuf = aBuf + ABYTES;
        const int sub = lane >> 3, r = lane & 7;
        const int mloc = m_base + (sub & 1)*8 + r;
        const int khalf = sub >> 1;
        const int msw = mloc & 7;
        const int kloc = lane & 15;
        const int nb = n_base >> 3;
        #pragma unroll
        for (int ks = 0; ks < 4; ks++) {
            uint32_t af[MI][4], bf[NI][2];
            #pragma unroll
            for (int mi = 0; mi < MI; mi++) {
                uint32_t addr = aBuf + (mloc + mi*16)*128 + (((ks*2 + khalf) ^ msw) << 4);
                ldsm_x4(af[mi], addr);
            }
            #pragma unroll
            for (int ni = 0; ni < NI; ni++) {
                int k = ks*16 + kloc;
                uint32_t addr = bBuf + k*(BN*2) + (((nb + ni) ^ (kloc & 7)) << 4);
                ldsm_x2t(bf[ni], addr);
            }
            #pragma unroll
            for (int mi = 0; mi < MI; mi++)
                #pragma unroll
                for (int ni = 0; ni < NI; ni++)
                    mma_bf16(acc[mi][ni], af[mi], bf[ni]);
        }
    };

    const int ntile = K / 64;
    stage(0, 0);
    if (ntile > 1) stage(1, 1);
    for (int kc = 0; kc < ntile; kc++) {
        if (kc + 1 < ntile) asm volatile("cp.async.wait_group 1;\n");
        else                asm volatile("cp.async.wait_group 0;\n");
        __syncthreads();
        compute(kc & 1);
        __syncthreads();
        if (kc + 2 < ntile) stage(kc + 2, kc & 1);
    }

    #pragma unroll
    for (int mi = 0; mi < MI; mi++) {
        int lr0 = m_base + mi*16 + g;
        int gr0 = m0 + lr0;
        int gr1 = gr0 + 8;
        #pragma unroll
        for (int ni = 0; ni < NI; ni++) {
            int lc = n_base + ni*8 + tin*2;
            int gc = n0 + lc;
            if (gc < N) {
                if (gr0 < M) {
                    float2 o = make_float2(acc[mi][ni][0], acc[mi][ni][1]);
                    if constexpr (ADD) { o.x += sC[lr0*BN + lc]; o.y += sC[lr0*BN + lc + 1]; }
                    *(float2*)(C + (size_t)gr0*N + gc) = o;
                }
                if (gr1 < M) {
                    float2 o = make_float2(acc[mi][ni][2], acc[mi][ni][3]);
                    if constexpr (ADD) { o.x += sC[(lr0+8)*BN + lc]; o.y += sC[(lr0+8)*BN + lc + 1]; }
                    *(float2*)(C + (size_t)gr1*N + gc) = o;
                }
            }
        }
    }
}

// ---------------- patchify + LN1 (writes bf16) ----------------------------------
__global__ void patchify_ln(const float* __restrict__ img,
                            const float* __restrict__ gg, const float* __restrict__ bb)
{
    __shared__ float sv[PD];
    __shared__ float red[8];
    int r = blockIdx.x;
    int b = r / NPATCH, p = r % NPATCH;
    int hh = p / 14, ww = p % 14;
    int tid = threadIdx.x;
    float lsum = 0.f;
    #pragma unroll
    for (int e = tid; e < PD; e += 256) {
        int c = e % 3, t = e / 3, p2 = t % 16, p1 = t / 16;
        float v = img[(((size_t)(b * 3 + c) * 224 + hh * 16 + p1) * 224) + ww * 16 + p2];
        sv[e] = v; lsum += v;
    }
    float mu = blockReduce256(lsum, red) * (1.f / PD);
    float lq = 0.f;
    #pragma unroll
    for (int e = tid; e < PD; e += 256) { float d = sv[e] - mu; lq += d * d; }
    float var = blockReduce256(lq, red) * (1.f / PD);
    float rs = rsqrtf(var + 1e-5f);
    #pragma unroll
    for (int e = tid; e < PD; e += 256)
        g_xpb[(size_t)r * PD + e] = __float2bfloat16((sv[e] - mu) * rs * gg[e] + bb[e]);
}

// ---------------- bias + LN2 + pos_emb + cls token (warp per row) --------------
// writes the initial residual into g_res
__global__ void pe2_posemb(const float* __restrict__ pe_b,
                           const float* __restrict__ g2, const float* __restrict__ b2,
                           const float* __restrict__ pos, const float* __restrict__ cls)
{
    int row = blockIdx.x * 8 + (threadIdx.x >> 5);
    int lane = threadIdx.x & 31;
    if (row < PROWS) {
        int b = row / NPATCH, p = row % NPATCH;
        const float4* xe4 = (const float4*)(g_xe + (size_t)row * DIMM);
        const float4* pb4 = (const float4*)pe_b;
        float4 v[2]; float s = 0.f;
        #pragma unroll
        for (int j = 0; j < 2; j++) {
            float4 t = xe4[lane + j*32], pb = pb4[lane + j*32];
            t.x += pb.x; t.y += pb.y; t.z += pb.z; t.w += pb.w;
            v[j] = t; s += t.x + t.y + t.z + t.w;
        }
        #pragma unroll
        for (int o = 16; o; o >>= 1) s += __shfl_xor_sync(0xffffffffu, s, o);
        float mu = s * (1.f / DIMM);
        float q = 0.f;
        #pragma unroll
        for (int j = 0; j < 2; j++) {
            float4 t = v[j];
            q += (t.x-mu)*(t.x-mu) + (t.y-mu)*(t.y-mu) + (t.z-mu)*(t.z-mu) + (t.w-mu)*(t.w-mu);
        }
        #pragma unroll
        for (int o = 16; o; o >>= 1) q += __shfl_xor_sync(0xffffffffu, q, o);
        float rs = rsqrtf(q * (1.f / DIMM) + 1e-5f);
        const float4* g4 = (const float4*)g2;
        const float4* bb4 = (const float4*)b2;
        const float4* pos4 = (const float4*)(pos + (size_t)(1 + p) * DIMM);
        float4* xo = (float4*)(g_res + ((size_t)(b * SEQ + 1 + p)) * DIMM);
        #pragma unroll
        for (int j = 0; j < 2; j++) {
            float4 t = v[j], w4 = g4[lane + j*32], bv = bb4[lane + j*32], pv = pos4[lane + j*32];
            float4 o4;
            o4.x = (t.x - mu) * rs * w4.x + bv.x + pv.x;
            o4.y = (t.y - mu) * rs * w4.y + bv.y + pv.y;
            o4.z = (t.z - mu) * rs * w4.z + bv.z + pv.z;
            o4.w = (t.w - mu) * rs * w4.w + bv.w + pv.w;
            xo[lane + j*32] = o4;
        }
    } else if (row < PROWS + BB) {
        int b = row - PROWS;
        const float4* c4 = (const float4*)cls;
        const float4* pos4 = (const float4*)pos;
        float4* xo = (float4*)(g_res + ((size_t)(b * SEQ)) * DIMM);
        #pragma unroll
        for (int j = 0; j < 2; j++) {
            float4 cv = c4[lane + j*32], pv = pos4[lane + j*32];
            xo[lane + j*32] = make_float4(cv.x+pv.x, cv.y+pv.y, cv.z+pv.z, cv.w+pv.w);
        }
    }
}

// ---------------- LN of residual (warp/row, float4 in, bf16 out) ----------------
__global__ void ln_res(const float* __restrict__ lw, const float* __restrict__ lb)
{
    int row = blockIdx.x * 8 + (threadIdx.x >> 5);
    int lane = threadIdx.x & 31;
    const float4* rr = (const float4*)(g_res + (size_t)row * DIMM);
    float4 v[2]; float s = 0.f;
    #pragma unroll
    for (int j = 0; j < 2; j++) {
        float4 t = rr[lane + j * 32];
        v[j] = t;
        s += t.x + t.y + t.z + t.w;
    }
    #pragma unroll
    for (int o = 16; o; o >>= 1) s += __shfl_xor_sync(0xffffffffu, s, o);
    float mu = s * (1.f / DIMM);
    float q = 0.f;
    #pragma unroll
    for (int j = 0; j < 2; j++) {
        float4 t = v[j];
        q += (t.x-mu)*(t.x-mu) + (t.y-mu)*(t.y-mu) + (t.z-mu)*(t.z-mu) + (t.w-mu)*(t.w-mu);
    }
    #pragma unroll
    for (int o = 16; o; o >>= 1) q += __shfl_xor_sync(0xffffffffu, q, o);
    float rs = rsqrtf(q * (1.f / DIMM) + 1e-5f);
    const float4* lw4 = (const float4*)lw;
    const float4* lb4 = (const float4*)lb;
    __nv_bfloat162* xo = (__nv_bfloat162*)(g_xnb + (size_t)row * DIMM);
    #pragma unroll
    for (int j = 0; j < 2; j++) {
        float4 t = v[j], w4 = lw4[lane + j*32], b4 = lb4[lane + j*32];
        float ox = (t.x - mu) * rs * w4.x + b4.x;
        float oy = (t.y - mu) * rs * w4.y + b4.y;
        float oz = (t.z - mu) * rs * w4.z + b4.z;
        float ow = (t.w - mu) * rs * w4.w + b4.w;
        xo[(lane + j*32)*2]     = __floats2bfloat162_rn(ox, oy);
        xo[(lane + j*32)*2 + 1] = __floats2bfloat162_rn(oz, ow);
    }
}

// ---------------- depthwise causal conv (k=4) + silu ----------------------------
__global__ void conv_silu(const float* __restrict__ cw, const float* __restrict__ cb)
{
    int i = blockIdx.x * 256 + threadIdx.x;
    if (i >= NROWS * DI / 4) return;
    int d4 = (i % (DI/4)) * 4;
    int row = i / (DI/4);
    int l = row % SEQ; int b = row / SEQ;
    float4 acc = *(const float4*)(cb + d4);
    #pragma unroll
    for (int k = 0; k < 4; k++) {
        int ll = l - 3 + k;
        if (ll >= 0) {
            float4 x4 = *(const float4*)(g_xz + ((size_t)(b * SEQ + ll)) * (2*DI) + d4);
            acc.x += x4.x * cw[(d4+0)*4 + k];
            acc.y += x4.y * cw[(d4+1)*4 + k];
            acc.z += x4.z * cw[(d4+2)*4 + k];
            acc.w += x4.w * cw[(d4+3)*4 + k];
        }
    }
    acc.x = siluf(acc.x); acc.y = siluf(acc.y); acc.z = siluf(acc.z); acc.w = siluf(acc.w);
    *(float4*)(g_uf + (size_t)row * DI + d4) = acc;
    __nv_bfloat162* ub = (__nv_bfloat162*)(g_ub + (size_t)row * DI + d4);
    ub[0] = __floats2bfloat162_rn(acc.x, acc.y);
    ub[1] = __floats2bfloat162_rn(acc.z, acc.w);
}

// ---------------- selective scan: full cp.async staging (dbc + u + z) -----------
__global__ void scan_k(const float* __restrict__ A_log, const float* __restrict__ Dpv,
                       const float* __restrict__ dtw, const float* __restrict__ dtb)
{
    __shared__ __align__(16) float sdbc[3][4][48];
    __shared__ __align__(16) float su  [3][4][64];
    __shared__ __align__(16) float sz  [3][4][64];
    int b = blockIdx.x >> 3;
    int chunk = blockIdx.x & 7;
    int tid = threadIdx.x;
    int d = chunk * 64 + (tid >> 1);
    int dloc = tid >> 1;
    int half = tid & 1;
    int n0 = half * 8;
    int row0 = b * SEQ;

    uint32_t dbcBase, uBase, zBase;
    asm("{.reg .u64 t; cvta.to.shared.u64 t, %1; cvt.u32.u64 %0, t;}" : "=r"(dbcBase) : "l"((void*)sdbc));
    asm("{.reg .u64 t; cvta.to.shared.u64 t, %1; cvt.u32.u64 %0, t;}" : "=r"(uBase) : "l"((void*)su));
    asm("{.reg .u64 t; cvta.to.shared.u64 t, %1; cvt.u32.u64 %0, t;}" : "=r"(zBase) : "l"((void*)sz));

    float A2[8], hst[8];
    #pragma unroll
    for (int j = 0; j < 8; j++) {
        A2[j] = -expf(A_log[(size_t)d * DS + n0 + j]) * LOG2E;
        hst[j] = 0.f;
    }
    float w16[16];
    #pragma unroll
    for (int k = 0; k < 16; k++) w16[k] = dtw[k * DI + d];
    float bias = dtb[d];
    float dpd = Dpv[d];

    const int NG = (SEQ + 3) / 4;
    const int ch0 = chunk * 64;

    // non-blocking staging: dbc 48 + u 64 + z 64 = 176 x 16B chunks per group
    auto stageA = [&](int grp) {
        int buf = grp % 3;
        #pragma unroll
        for (int pass = 0; pass < 2; pass++) {
            int c = tid + pass * 128;
            if (c < 48) {
                int r = c / 12, off = c % 12;
                int l = grp * 4 + r;
                if (l < SEQ) {
                    uint32_t dst = dbcBase + (((buf * 4 + r) * 48) + off * 4) * 4;
                    cp16(dst, g_dbc + (size_t)(row0 + l) * 48 + off * 4, 16);
                }
            } else if (c < 112) {
                int c2 = c - 48;
                int r = c2 / 16, off = c2 % 16;
                int l = grp * 4 + r;
                if (l < SEQ) {
                    uint32_t dst = uBase + (((buf * 4 + r) * 64) + off * 4) * 4;
                    cp16(dst, g_uf + (size_t)(row0 + l) * DI + ch0 + off * 4, 16);
                }
            } else if (c < 176) {
                int c3 = c - 112;
                int r = c3 / 16, off = c3 % 16;
                int l = grp * 4 + r;
                if (l < SEQ) {
                    uint32_t dst = zBase + (((buf * 4 + r) * 64) + off * 4) * 4;
                    cp16(dst, g_xz + (size_t)(row0 + l) * (2*DI) + DI + ch0 + off * 4, 16);
                }
            }
        }
        asm volatile("cp.async.commit_group;\n");
    };

    stageA(0);
    if (NG > 1) stageA(1);

    for (int grp = 0; grp < NG; grp++) {
        if (grp + 1 < NG) asm volatile("cp.async.wait_group 1;\n");
        else              asm volatile("cp.async.wait_group 0;\n");
        __syncthreads();
        if (grp + 2 < NG) stageA(grp + 2);
        int buf = grp % 3;
        #pragma unroll
        for (int g2 = 0; g2 < 4; g2++) {
            int l = grp * 4 + g2;
            if (l < SEQ) {
                float uv = su[buf][g2][dloc];
                float acc = bias;
                #pragma unroll
                for (int k = 0; k < 16; k++) acc += sdbc[buf][g2][k] * w16[k];
                float dt = softplusf(acc);
                float xt = dt * uv;
                float y = 0.f;
                #pragma unroll
                for (int j = 0; j < 8; j++) {
                    float dA = fex2(dt * A2[j]);
                    float hv = dA * hst[j] + xt * sdbc[buf][g2][16 + n0 + j];
                    hst[j] = hv;
                    y += hv * sdbc[buf][g2][32 + n0 + j];
                }
                y += __shfl_xor_sync(0xffffffffu, y, 1);
                if (!half) {
                    float zv = sz[buf][g2][dloc];
                    g_yb[(size_t)(row0 + l) * DI + d] =
                        __float2bfloat16((y + uv * dpd) * siluf(zv));
                }
            }
        }
        __syncthreads();
    }
}

// ---------------- final LN on token 0 + head (fused) ----------------------------
__global__ void lnhead_k(const float* __restrict__ gw, const float* __restrict__ gb,
                         const float* __restrict__ hw, const float* __restrict__ hb,
                         float* __restrict__ out)
{
    __shared__ float red[8];
    __shared__ float sx[DIMM];
    int b = blockIdx.x; int c = threadIdx.x;
    size_t idx = (size_t)(b * SEQ) * DIMM + c;
    float v = g_res[idx];
    float mu = blockReduce256(v, red) * (1.f / DIMM);
    float d = v - mu;
    float var = blockReduce256(d * d, red) * (1.f / DIMM);
    sx[c] = d * rsqrtf(var + 1e-5f) * gw[c] + gb[c];
    __syncthreads();
    for (int n = c; n < NCLS; n += 256) {
        float acc = hb[n];
        #pragma unroll 4
        for (int k = 0; k < DIMM; k++) acc += sx[k] * hw[(size_t)k * NCLS + n];
        out[(size_t)b * NCLS + n] = acc;
    }
}

// ---------------- launch ---------------------------------------------------------
extern "C" void kernel_launch(void* const* d_in, const int* in_sizes, int n_in,
                              void* d_out, int out_size)
{
    (void)in_sizes; (void)n_in; (void)out_size;
    const float* img      = (const float*)d_in[0];
    const float* pe_ln1_g = (const float*)d_in[1];
    const float* pe_ln1_b = (const float*)d_in[2];
    const float* pe_w     = (const float*)d_in[3];
    const float* pe_b     = (const float*)d_in[4];
    const float* pe_ln2_g = (const float*)d_in[5];
    const float* pe_ln2_b = (const float*)d_in[6];
    const float* pos_emb  = (const float*)d_in[7];
    const float* cls_tok  = (const float*)d_in[8];
    const float* ln_w     = (const float*)d_in[9];
    const float* ln_b     = (const float*)d_in[10];
    const float* in_w     = (const float*)d_in[11];
    const float* conv_w   = (const float*)d_in[12];
    const float* conv_b   = (const float*)d_in[13];
    const float* xproj_w  = (const float*)d_in[14];
    const float* dtproj_w = (const float*)d_in[15];
    const float* dtproj_b = (const float*)d_in[16];
    const float* A_log    = (const float*)d_in[17];
    const float* Dp       = (const float*)d_in[18];
    const float* out_w    = (const float*)d_in[19];
    const float* normf_w  = (const float*)d_in[20];
    const float* normf_b  = (const float*)d_in[21];
    const float* head_w   = (const float*)d_in[22];
    const float* head_b   = (const float*)d_in[23];
    float* out = (float*)d_out;

    __nv_bfloat16 *p_xpb, *p_xnb, *p_ub, *p_yb, *p_wpe, *p_win, *p_wxp, *p_wout;
    float *p_xe, *p_xz, *p_res, *p_dbc;
    cudaGetSymbolAddress((void**)&p_xpb, g_xpb);
    cudaGetSymbolAddress((void**)&p_xnb, g_xnb);
    cudaGetSymbolAddress((void**)&p_ub , g_ub );
    cudaGetSymbolAddress((void**)&p_yb , g_yb );
    cudaGetSymbolAddress((void**)&p_wpe, w_pe );
    cudaGetSymbolAddress((void**)&p_win, w_in );
    cudaGetSymbolAddress((void**)&p_wxp, w_xp );
    cudaGetSymbolAddress((void**)&p_wout, w_out);
    cudaGetSymbolAddress((void**)&p_xe , g_xe );
    cudaGetSymbolAddress((void**)&p_xz , g_xz );
    cudaGetSymbolAddress((void**)&p_res, g_res);
    cudaGetSymbolAddress((void**)&p_dbc, g_dbc);

    const int SMEM_BIG   = 2 * (128*128 + 64*128*2);           // 65536 (<128,128>)
    const int SMEM_SMALL = 2 * (64*128 + 64*64*2);             // 32768 (<64,64>)
    const int SMEM_ADD   = SMEM_SMALL + 64*64*4;               // 49152 (<64,64> + C tile)
    cudaFuncSetAttribute((const void*)mmabf16<128,128,64,32,false>,
                         cudaFuncAttributeMaxDynamicSharedMemorySize, SMEM_BIG);
    cudaFuncSetAttribute((const void*)mmabf16<64,64,32,32,false>,
                         cudaFuncAttributeMaxDynamicSharedMemorySize, SMEM_SMALL);
    cudaFuncSetAttribute((const void*)mmabf16<64,64,32,32,true>,
                         cudaFuncAttributeMaxDynamicSharedMemorySize, SMEM_ADD);

    // weight conversion (single kernel)
    {
        int total4 = (PD*DIMM + NL*DIMM*2*DI + NL*DI*48 + NL*DI*DIMM) / 4;
        cvt_all<<<(total4 + 255)/256, 256>>>(pe_w, in_w, xproj_w, out_w,
                                             p_wpe, p_win, p_wxp, p_wout);
    }

    // patch embed
    patchify_ln<<<PROWS, 256>>>(img, pe_ln1_g, pe_ln1_b);
    {   // g_xe = g_xpb @ w_pe  (3136 x 256 x 768)
        dim3 grid(DIMM / 64, PROWS / 64);
        mmabf16<64,64,32,32,false><<<grid, 128, SMEM_SMALL>>>(p_xpb, p_wpe, p_xe,
                                                              PROWS, DIMM, PD);
    }
    pe2_posemb<<<(PROWS + BB + 7) / 8, 256>>>(pe_b, pe_ln2_g, pe_ln2_b, pos_emb, cls_tok);

    for (int i = 0; i < 8; i++) {
        ln_res<<<NROWS / 8, 256>>>(ln_w + i * DIMM, ln_b + i * DIMM);
        {   // g_xz = g_xnb @ w_in[i]  (3152 x 1024 x 256) -> fp32
            dim3 grid((2 * DI) / 128, (NROWS + 127) / 128);
            mmabf16<128,128,64,32,false><<<grid, 256, SMEM_BIG>>>(
                p_xnb, p_win + (size_t)i * DIMM * 2 * DI, p_xz,
                NROWS, 2 * DI, DIMM);
        }
        conv_silu<<<(NROWS * DI / 4 + 255) / 256, 256>>>(conv_w + (size_t)i * DI * 4, conv_b + i * DI);
        {   // g_dbc = g_ub @ w_xp[i]  (3152 x 48 x 512)
            dim3 grid(1, (NROWS + 63) / 64);
            mmabf16<64,64,32,32,false><<<grid, 128, SMEM_SMALL>>>(
                p_ub, p_wxp + (size_t)i * DI * 48, p_dbc, NROWS, 48, DI);
        }
        scan_k<<<BB * 8, 128>>>(A_log + (size_t)i * DI * DS, Dp + i * DI,
                                dtproj_w + (size_t)i * 16 * DI, dtproj_b + i * DI);
        {   // g_res += g_yb @ w_out[i]  (3152 x 256 x 512), fused residual (prefetched)
            dim3 grid(DIMM / 64, (NROWS + 63) / 64);
            mmabf16<64,64,32,32,true><<<grid, 128, SMEM_ADD>>>(
                p_yb, p_wout + (size_t)i * DI * DIMM, p_res, NROWS, DIMM, DI);
        }
    }

    lnhead_k<<<BB, 256>>>(normf_w, normf_b, head_w, head_b, out);
}

// round 17
// speedup vs baseline: 1.0803x; 1.0078x over previous
#include <cuda_runtime.h>
#include <cuda_bf16.h>
#include <math.h>
#include <stdint.h>

#define BB 16
#define SEQ 197
#define NROWS (BB*SEQ)        // 3152
#define DIMM 256
#define DI 512
#define DS 16
#define PD 768
#define NPATCH 196
#define PROWS (BB*NPATCH)     // 3136
#define NCLS 1000
#define NL 8

// ---------------- scratch (device globals; no allocation allowed) -------------
__device__ __align__(256) __nv_bfloat16 g_xpb[PROWS*PD];
__device__ __align__(256) float g_xe [PROWS*DIMM];
__device__ __align__(256) float g_res[NROWS*DIMM];
__device__ __align__(256) __nv_bfloat16 g_xnb[NROWS*DIMM];
__device__ __align__(256) float g_xz [NROWS*2*DI];
__device__ __align__(256) __nv_bfloat16 g_ub [NROWS*DI];     // conv out bf16 (GEMM A)
__device__ __align__(256) float g_uf [NROWS*DI];             // conv out fp32 (scan)
__device__ __align__(256) float g_dbc[NROWS*48];
__device__ __align__(256) __nv_bfloat16 g_yb [NROWS*DI];

// bf16 weights (converted per launch)
__device__ __align__(256) __nv_bfloat16 w_pe [PD*DIMM];
__device__ __align__(256) __nv_bfloat16 w_in [NL*DIMM*2*DI];
__device__ __align__(256) __nv_bfloat16 w_xp [NL*DI*48];
__device__ __align__(256) __nv_bfloat16 w_out[NL*DI*DIMM];

// ---------------- fast math helpers -------------------------------------------
__device__ __forceinline__ float fex2(float x){ float y; asm("ex2.approx.ftz.f32 %0,%1;":"=f"(y):"f"(x)); return y; }
__device__ __forceinline__ float flg2(float x){ float y; asm("lg2.approx.ftz.f32 %0,%1;":"=f"(y):"f"(x)); return y; }
__device__ __forceinline__ float frcp(float x){ float y; asm("rcp.approx.ftz.f32 %0,%1;":"=f"(y):"f"(x)); return y; }
#define LOG2E 1.4426950408889634f
#define LN2   0.6931471805599453f
__device__ __forceinline__ float siluf(float x){ return x * frcp(1.f + fex2(-x * LOG2E)); }
__device__ __forceinline__ float softplusf(float x){
    return (x > 20.f) ? x : LN2 * flg2(1.f + fex2(x * LOG2E));
}

__device__ __forceinline__ float blockReduce256(float v, float* red) {
    int lane = threadIdx.x & 31, w = threadIdx.x >> 5;
    #pragma unroll
    for (int o = 16; o; o >>= 1) v += __shfl_xor_sync(0xffffffffu, v, o);
    __syncthreads();
    if (lane == 0) red[w] = v;
    __syncthreads();
    float t = 0.f;
    if (w == 0) {
        t = (lane < 8) ? red[lane] : 0.f;
        #pragma unroll
        for (int o = 4; o; o >>= 1) t += __shfl_xor_sync(0xffffffffu, t, o);
        if (lane == 0) red[0] = t;
    }
    __syncthreads();
    float r = red[0];
    __syncthreads();
    return r;
}

// ---------------- merged weight convert ----------------------------------------
__global__ void cvt_all(const float* __restrict__ pe, const float* __restrict__ inw,
                        const float* __restrict__ xp, const float* __restrict__ ow,
                        __nv_bfloat16* ope, __nv_bfloat16* oin,
                        __nv_bfloat16* oxp, __nv_bfloat16* oow)
{
    int i = blockIdx.x * 256 + threadIdx.x;
    const int c0 = PD*DIMM/4, c1 = NL*DIMM*2*DI/4, c2 = NL*DI*48/4, c3 = NL*DI*DIMM/4;
    const float* src; __nv_bfloat16* dst;
    if (i < c0) { src = pe; dst = ope; }
    else if ((i -= c0) < c1) { src = inw; dst = oin; }
    else if ((i -= c1) < c2) { src = xp; dst = oxp; }
    else if ((i -= c2) < c3) { src = ow; dst = oow; }
    else return;
    float4 v = ((const float4*)src)[i];
    ((__nv_bfloat162*)dst)[2*i]   = __floats2bfloat162_rn(v.x, v.y);
    ((__nv_bfloat162*)dst)[2*i+1] = __floats2bfloat162_rn(v.z, v.w);
}

// ---------------- bf16 tensor-core GEMM (cp.async 2-stage + ldmatrix) ----------
__device__ __forceinline__ void ldsm_x4(uint32_t a[4], uint32_t addr){
    asm volatile("ldmatrix.sync.aligned.m8n8.x4.shared.b16 {%0,%1,%2,%3}, [%4];"
        : "=r"(a[0]),"=r"(a[1]),"=r"(a[2]),"=r"(a[3]) : "r"(addr));
}
__device__ __forceinline__ void ldsm_x2t(uint32_t b[2], uint32_t addr){
    asm volatile("ldmatrix.sync.aligned.m8n8.x2.trans.shared.b16 {%0,%1}, [%2];"
        : "=r"(b[0]),"=r"(b[1]) : "r"(addr));
}
__device__ __forceinline__ void mma_bf16(float c[4], const uint32_t a[4], const uint32_t b[2]){
    asm volatile(
        "mma.sync.aligned.m16n8k16.row.col.f32.bf16.bf16.f32 "
        "{%0,%1,%2,%3},{%4,%5,%6,%7},{%8,%9},{%0,%1,%2,%3};\n"
        : "+f"(c[0]), "+f"(c[1]), "+f"(c[2]), "+f"(c[3])
        : "r"(a[0]), "r"(a[1]), "r"(a[2]), "r"(a[3]), "r"(b[0]), "r"(b[1]));
}
__device__ __forceinline__ void cp16(uint32_t dst, const void* src, int srcbytes){
    asm volatile("cp.async.cg.shared.global [%0], [%1], 16, %2;\n"
        :: "r"(dst), "l"(src), "r"(srcbytes));
}

// ADD=true: C += result; the C tile is prefetched into SMEM via cp.async before
// the K-loop (race-free: 1 thread per element).
template<int BM, int BN, int WM, int WN, bool ADD>
__global__ void __launch_bounds__((BM/WM)*(BN/WN)*32)
mmabf16(const __nv_bfloat16* __restrict__ A, const __nv_bfloat16* __restrict__ B,
        float* __restrict__ C, int M, int N, int K)
{
    constexpr int WARPS_M = BM/WM, WARPS_N = BN/WN;
    constexpr int NTHR = WARPS_M*WARPS_N*32;
    constexpr int MI = WM/16, NI = WN/8;
    constexpr int ABYTES = BM*128;
    constexpr int BBYTES = 64*BN*2;
    constexpr int BUF = ABYTES + BBYTES;
    constexpr int A_OPS = BM*8/NTHR;
    constexpr int BN8 = BN/8;
    constexpr int B_OPS = 64*BN8/NTHR;
    constexpr int C_CHUNKS = BM*BN/4;           // 16B chunks of C tile

    extern __shared__ char smc[];
    uint32_t smBase;
    asm("{.reg .u64 t; cvta.to.shared.u64 t, %1; cvt.u32.u64 %0, t;}" : "=r"(smBase) : "l"(smc));
    const uint32_t cBase = smBase + 2*BUF;      // C tile (ADD only)
    float* sC = (float*)(smc + 2*BUF);

    const int tid = threadIdx.x;
    const int lane = tid & 31, warp = tid >> 5;
    const int g = lane >> 2, tin = lane & 3;
    const int wm = warp % WARPS_M, wn = warp / WARPS_M;
    const int m_base = wm*WM, n_base = wn*WN;
    const int m0 = blockIdx.y * BM, n0 = blockIdx.x * BN;

    // prefetch residual C tile (ADD): own commit group, drains under mainloop
    if constexpr (ADD) {
        #pragma unroll
        for (int i = 0; i < C_CHUNKS / NTHR; i++) {
            int idx = tid + i * NTHR;
            int m = idx / (BN/4), c4 = idx % (BN/4);
            int gm = m0 + m;
            int sz = (gm < M) ? 16 : 0;
            int gmc = (gm < M) ? gm : (M-1);
            cp16(cBase + (m * BN + c4*4) * 4, C + (size_t)gmc*N + n0 + c4*4, sz);
        }
        asm volatile("cp.async.commit_group;\n");
    }

    float acc[MI][NI][4];
    #pragma unroll
    for (int i = 0; i < MI; i++)
        #pragma unroll
        for (int j = 0; j < NI; j++)
            #pragma unroll
            for (int t = 0; t < 4; t++) acc[i][j][t] = 0.f;

    auto stage = [&](int kc, int buf) {
        #pragma unroll
        for (int i = 0; i < A_OPS; i++) {
            int idx = tid + i*NTHR;
            int m = idx >> 3, c = idx & 7;
            int gm = m0 + m;
            int sz = (gm < M) ? 16 : 0;
            int gmc = (gm < M) ? gm : (M-1);
            uint32_t dst = smBase + buf*BUF + m*128 + ((c ^ (m & 7)) << 4);
            cp16(dst, A + (size_t)gmc*K + kc*64 + c*8, sz);
        }
        #pragma unroll
        for (int i = 0; i < B_OPS; i++) {
            int idx = tid + i*NTHR;
            int nc = idx % BN8, k = idx / BN8;
            int gn = n0 + nc*8;
            int sz = (gn < N) ? 16 : 0;
            int gnc = (gn < N) ? gn : 0;
            uint32_t dst = smBase + buf*BUF + ABYTES + k*(BN*2) + ((nc ^ (k & 7)) << 4);
            cp16(dst, B + (size_t)(kc*64 + k)*N + gnc, sz);
        }
        asm volatile("cp.async.commit_group;\n");
    };

    auto compute = [&](int buf) {
        const uint32_t aBuf = smBase + buf*BUF;
        const uint32_t bBuf = aBuf + ABYTES;
        const int sub = lane >> 3, r = lane & 7;
        const int mloc = m_base + (sub & 1)*8 + r;
        const int khalf = sub >> 1;
        const int msw = mloc & 7;
        const int kloc = lane & 15;
        const int nb = n_base >> 3;
        #pragma unroll
        for (int ks = 0; ks < 4; ks++) {
            uint32_t af[MI][4], bf[NI][2];
            #pragma unroll
            for (int mi = 0; mi < MI; mi++) {
                uint32_t addr = aBuf + (mloc + mi*16)*128 + (((ks*2 + khalf) ^ msw) << 4);
                ldsm_x4(af[mi], addr);
            }
            #pragma unroll
            for (int ni = 0; ni < NI; ni++) {
                int k = ks*16 + kloc;
                uint32_t addr = bBuf + k*(BN*2) + (((nb + ni) ^ (kloc & 7)) << 4);
                ldsm_x2t(bf[ni], addr);
            }
            #pragma unroll
            for (int mi = 0; mi < MI; mi++)
                #pragma unroll
                for (int ni = 0; ni < NI; ni++)
                    mma_bf16(acc[mi][ni], af[mi], bf[ni]);
        }
    };

    const int ntile = K / 64;
    stage(0, 0);
    if (ntile > 1) stage(1, 1);
    for (int kc = 0; kc < ntile; kc++) {
        if (kc + 1 < ntile) asm volatile("cp.async.wait_group 1;\n");
        else                asm volatile("cp.async.wait_group 0;\n");
        __syncthreads();
        compute(kc & 1);
        __syncthreads();
        if (kc + 2 < ntile) stage(kc + 2, kc & 1);
    }

    #pragma unroll
    for (int mi = 0; mi < MI; mi++) {
        int lr0 = m_base + mi*16 + g;
        int gr0 = m0 + lr0;
        int gr1 = gr0 + 8;
        #pragma unroll
        for (int ni = 0; ni < NI; ni++) {
            int lc = n_base + ni*8 + tin*2;
            int gc = n0 + lc;
            if (gc < N) {
                if (gr0 < M) {
                    float2 o = make_float2(acc[mi][ni][0], acc[mi][ni][1]);
                    if constexpr (ADD) { o.x += sC[lr0*BN + lc]; o.y += sC[lr0*BN + lc + 1]; }
                    *(float2*)(C + (size_t)gr0*N + gc) = o;
                }
                if (gr1 < M) {
                    float2 o = make_float2(acc[mi][ni][2], acc[mi][ni][3]);
                    if constexpr (ADD) { o.x += sC[(lr0+8)*BN + lc]; o.y += sC[(lr0+8)*BN + lc + 1]; }
                    *(float2*)(C + (size_t)gr1*N + gc) = o;
                }
            }
        }
    }
}

// ---------------- patchify + LN1 (writes bf16) ----------------------------------
__global__ void patchify_ln(const float* __restrict__ img,
                            const float* __restrict__ gg, const float* __restrict__ bb)
{
    __shared__ float sv[PD];
    __shared__ float red[8];
    int r = blockIdx.x;
    int b = r / NPATCH, p = r % NPATCH;
    int hh = p / 14, ww = p % 14;
    int tid = threadIdx.x;
    float lsum = 0.f;
    #pragma unroll
    for (int e = tid; e < PD; e += 256) {
        int c = e % 3, t = e / 3, p2 = t % 16, p1 = t / 16;
        float v = img[(((size_t)(b * 3 + c) * 224 + hh * 16 + p1) * 224) + ww * 16 + p2];
        sv[e] = v; lsum += v;
    }
    float mu = blockReduce256(lsum, red) * (1.f / PD);
    float lq = 0.f;
    #pragma unroll
    for (int e = tid; e < PD; e += 256) { float d = sv[e] - mu; lq += d * d; }
    float var = blockReduce256(lq, red) * (1.f / PD);
    float rs = rsqrtf(var + 1e-5f);
    #pragma unroll
    for (int e = tid; e < PD; e += 256)
        g_xpb[(size_t)r * PD + e] = __float2bfloat16((sv[e] - mu) * rs * gg[e] + bb[e]);
}

// ---------------- bias + LN2 + pos_emb + cls token (warp per row) --------------
// writes the initial residual into g_res
__global__ void pe2_posemb(const float* __restrict__ pe_b,
                           const float* __restrict__ g2, const float* __restrict__ b2,
                           const float* __restrict__ pos, const float* __restrict__ cls)
{
    int row = blockIdx.x * 8 + (threadIdx.x >> 5);
    int lane = threadIdx.x & 31;
    if (row < PROWS) {
        int b = row / NPATCH, p = row % NPATCH;
        const float4* xe4 = (const float4*)(g_xe + (size_t)row * DIMM);
        const float4* pb4 = (const float4*)pe_b;
        float4 v[2]; float s = 0.f;
        #pragma unroll
        for (int j = 0; j < 2; j++) {
            float4 t = xe4[lane + j*32], pb = pb4[lane + j*32];
            t.x += pb.x; t.y += pb.y; t.z += pb.z; t.w += pb.w;
            v[j] = t; s += t.x + t.y + t.z + t.w;
        }
        #pragma unroll
        for (int o = 16; o; o >>= 1) s += __shfl_xor_sync(0xffffffffu, s, o);
        float mu = s * (1.f / DIMM);
        float q = 0.f;
        #pragma unroll
        for (int j = 0; j < 2; j++) {
            float4 t = v[j];
            q += (t.x-mu)*(t.x-mu) + (t.y-mu)*(t.y-mu) + (t.z-mu)*(t.z-mu) + (t.w-mu)*(t.w-mu);
        }
        #pragma unroll
        for (int o = 16; o; o >>= 1) q += __shfl_xor_sync(0xffffffffu, q, o);
        float rs = rsqrtf(q * (1.f / DIMM) + 1e-5f);
        const float4* g4 = (const float4*)g2;
        const float4* bb4 = (const float4*)b2;
        const float4* pos4 = (const float4*)(pos + (size_t)(1 + p) * DIMM);
        float4* xo = (float4*)(g_res + ((size_t)(b * SEQ + 1 + p)) * DIMM);
        #pragma unroll
        for (int j = 0; j < 2; j++) {
            float4 t = v[j], w4 = g4[lane + j*32], bv = bb4[lane + j*32], pv = pos4[lane + j*32];
            float4 o4;
            o4.x = (t.x - mu) * rs * w4.x + bv.x + pv.x;
            o4.y = (t.y - mu) * rs * w4.y + bv.y + pv.y;
            o4.z = (t.z - mu) * rs * w4.z + bv.z + pv.z;
            o4.w = (t.w - mu) * rs * w4.w + bv.w + pv.w;
            xo[lane + j*32] = o4;
        }
    } else if (row < PROWS + BB) {
        int b = row - PROWS;
        const float4* c4 = (const float4*)cls;
        const float4* pos4 = (const float4*)pos;
        float4* xo = (float4*)(g_res + ((size_t)(b * SEQ)) * DIMM);
        #pragma unroll
        for (int j = 0; j < 2; j++) {
            float4 cv = c4[lane + j*32], pv = pos4[lane + j*32];
            xo[lane + j*32] = make_float4(cv.x+pv.x, cv.y+pv.y, cv.z+pv.z, cv.w+pv.w);
        }
    }
}

// ---------------- LN of residual (warp/row, float4 in, bf16 out) ----------------
__global__ void ln_res(const float* __restrict__ lw, const float* __restrict__ lb)
{
    int row = blockIdx.x * 8 + (threadIdx.x >> 5);
    int lane = threadIdx.x & 31;
    const float4* rr = (const float4*)(g_res + (size_t)row * DIMM);
    float4 v[2]; float s = 0.f;
    #pragma unroll
    for (int j = 0; j < 2; j++) {
        float4 t = rr[lane + j * 32];
        v[j] = t;
        s += t.x + t.y + t.z + t.w;
    }
    #pragma unroll
    for (int o = 16; o; o >>= 1) s += __shfl_xor_sync(0xffffffffu, s, o);
    float mu = s * (1.f / DIMM);
    float q = 0.f;
    #pragma unroll
    for (int j = 0; j < 2; j++) {
        float4 t = v[j];
        q += (t.x-mu)*(t.x-mu) + (t.y-mu)*(t.y-mu) + (t.z-mu)*(t.z-mu) + (t.w-mu)*(t.w-mu);
    }
    #pragma unroll
    for (int o = 16; o; o >>= 1) q += __shfl_xor_sync(0xffffffffu, q, o);
    float rs = rsqrtf(q * (1.f / DIMM) + 1e-5f);
    const float4* lw4 = (const float4*)lw;
    const float4* lb4 = (const float4*)lb;
    __nv_bfloat162* xo = (__nv_bfloat162*)(g_xnb + (size_t)row * DIMM);
    #pragma unroll
    for (int j = 0; j < 2; j++) {
        float4 t = v[j], w4 = lw4[lane + j*32], b4 = lb4[lane + j*32];
        float ox = (t.x - mu) * rs * w4.x + b4.x;
        float oy = (t.y - mu) * rs * w4.y + b4.y;
        float oz = (t.z - mu) * rs * w4.z + b4.z;
        float ow = (t.w - mu) * rs * w4.w + b4.w;
        xo[(lane + j*32)*2]     = __floats2bfloat162_rn(ox, oy);
        xo[(lane + j*32)*2 + 1] = __floats2bfloat162_rn(oz, ow);
    }
}

// ---------------- depthwise causal conv (k=4) + silu ----------------------------
__global__ void conv_silu(const float* __restrict__ cw, const float* __restrict__ cb)
{
    int i = blockIdx.x * 256 + threadIdx.x;
    if (i >= NROWS * DI / 4) return;
    int d4 = (i % (DI/4)) * 4;
    int row = i / (DI/4);
    int l = row % SEQ; int b = row / SEQ;
    float4 acc = *(const float4*)(cb + d4);
    #pragma unroll
    for (int k = 0; k < 4; k++) {
        int ll = l - 3 + k;
        if (ll >= 0) {
            float4 x4 = *(const float4*)(g_xz + ((size_t)(b * SEQ + ll)) * (2*DI) + d4);
            acc.x += x4.x * cw[(d4+0)*4 + k];
            acc.y += x4.y * cw[(d4+1)*4 + k];
            acc.z += x4.z * cw[(d4+2)*4 + k];
            acc.w += x4.w * cw[(d4+3)*4 + k];
        }
    }
    acc.x = siluf(acc.x); acc.y = siluf(acc.y); acc.z = siluf(acc.z); acc.w = siluf(acc.w);
    *(float4*)(g_uf + (size_t)row * DI + d4) = acc;
    __nv_bfloat162* ub = (__nv_bfloat162*)(g_ub + (size_t)row * DI + d4);
    ub[0] = __floats2bfloat162_rn(acc.x, acc.y);
    ub[1] = __floats2bfloat162_rn(acc.z, acc.w);
}

// ---------------- selective scan: full cp.async staging (dbc + u + z) -----------
__global__ void scan_k(const float* __restrict__ A_log, const float* __restrict__ Dpv,
                       const float* __restrict__ dtw, const float* __restrict__ dtb)
{
    __shared__ __align__(16) float sdbc[3][4][48];
    __shared__ __align__(16) float su  [3][4][64];
    __shared__ __align__(16) float sz  [3][4][64];
    int b = blockIdx.x >> 3;
    int chunk = blockIdx.x & 7;
    int tid = threadIdx.x;
    int d = chunk * 64 + (tid >> 1);
    int dloc = tid >> 1;
    int half = tid & 1;
    int n0 = half * 8;
    int row0 = b * SEQ;

    uint32_t dbcBase, uBase, zBase;
    asm("{.reg .u64 t; cvta.to.shared.u64 t, %1; cvt.u32.u64 %0, t;}" : "=r"(dbcBase) : "l"((void*)sdbc));
    asm("{.reg .u64 t; cvta.to.shared.u64 t, %1; cvt.u32.u64 %0, t;}" : "=r"(uBase) : "l"((void*)su));
    asm("{.reg .u64 t; cvta.to.shared.u64 t, %1; cvt.u32.u64 %0, t;}" : "=r"(zBase) : "l"((void*)sz));

    float A2[8], hst[8];
    #pragma unroll
    for (int j = 0; j < 8; j++) {
        A2[j] = -expf(A_log[(size_t)d * DS + n0 + j]) * LOG2E;
        hst[j] = 0.f;
    }
    float w16[16];
    #pragma unroll
    for (int k = 0; k < 16; k++) w16[k] = dtw[k * DI + d];
    float bias = dtb[d];
    float dpd = Dpv[d];

    const int NG = (SEQ + 3) / 4;
    const int ch0 = chunk * 64;

    // non-blocking staging: dbc 48 + u 64 + z 64 = 176 x 16B chunks per group
    auto stageA = [&](int grp) {
        int buf = grp % 3;
        #pragma unroll
        for (int pass = 0; pass < 2; pass++) {
            int c = tid + pass * 128;
            if (c < 48) {
                int r = c / 12, off = c % 12;
                int l = grp * 4 + r;
                if (l < SEQ) {
                    uint32_t dst = dbcBase + (((buf * 4 + r) * 48) + off * 4) * 4;
                    cp16(dst, g_dbc + (size_t)(row0 + l) * 48 + off * 4, 16);
                }
            } else if (c < 112) {
                int c2 = c - 48;
                int r = c2 / 16, off = c2 % 16;
                int l = grp * 4 + r;
                if (l < SEQ) {
                    uint32_t dst = uBase + (((buf * 4 + r) * 64) + off * 4) * 4;
                    cp16(dst, g_uf + (size_t)(row0 + l) * DI + ch0 + off * 4, 16);
                }
            } else if (c < 176) {
                int c3 = c - 112;
                int r = c3 / 16, off = c3 % 16;
                int l = grp * 4 + r;
                if (l < SEQ) {
                    uint32_t dst = zBase + (((buf * 4 + r) * 64) + off * 4) * 4;
                    cp16(dst, g_xz + (size_t)(row0 + l) * (2*DI) + DI + ch0 + off * 4, 16);
                }
            }
        }
        asm volatile("cp.async.commit_group;\n");
    };

    stageA(0);
    if (NG > 1) stageA(1);

    for (int grp = 0; grp < NG; grp++) {
        if (grp + 1 < NG) asm volatile("cp.async.wait_group 1;\n");
        else              asm volatile("cp.async.wait_group 0;\n");
        __syncthreads();
        if (grp + 2 < NG) stageA(grp + 2);
        int buf = grp % 3;
        #pragma unroll
        for (int g2 = 0; g2 < 4; g2++) {
            int l = grp * 4 + g2;
            if (l < SEQ) {
                float uv = su[buf][g2][dloc];
                float acc = bias;
                #pragma unroll
                for (int k = 0; k < 16; k++) acc += sdbc[buf][g2][k] * w16[k];
                float dt = softplusf(acc);
                float xt = dt * uv;
                float y = 0.f;
                #pragma unroll
                for (int j = 0; j < 8; j++) {
                    float dA = fex2(dt * A2[j]);
                    float hv = dA * hst[j] + xt * sdbc[buf][g2][16 + n0 + j];
                    hst[j] = hv;
                    y += hv * sdbc[buf][g2][32 + n0 + j];
                }
                y += __shfl_xor_sync(0xffffffffu, y, 1);
                if (!half) {
                    float zv = sz[buf][g2][dloc];
                    g_yb[(size_t)(row0 + l) * DI + d] =
                        __float2bfloat16((y + uv * dpd) * siluf(zv));
                }
            }
        }
        __syncthreads();
    }
}

// ---------------- final LN on token 0 + head (fused) ----------------------------
__global__ void lnhead_k(const float* __restrict__ gw, const float* __restrict__ gb,
                         const float* __restrict__ hw, const float* __restrict__ hb,
                         float* __restrict__ out)
{
    __shared__ float red[8];
    __shared__ float sx[DIMM];
    int b = blockIdx.x; int c = threadIdx.x;
    size_t idx = (size_t)(b * SEQ) * DIMM + c;
    float v = g_res[idx];
    float mu = blockReduce256(v, red) * (1.f / DIMM);
    float d = v - mu;
    float var = blockReduce256(d * d, red) * (1.f / DIMM);
    sx[c] = d * rsqrtf(var + 1e-5f) * gw[c] + gb[c];
    __syncthreads();
    for (int n = c; n < NCLS; n += 256) {
        float acc = hb[n];
        #pragma unroll 4
        for (int k = 0; k < DIMM; k++) acc += sx[k] * hw[(size_t)k * NCLS + n];
        out[(size_t)b * NCLS + n] = acc;
    }
}

// ---------------- launch ---------------------------------------------------------
extern "C" void kernel_launch(void* const* d_in, const int* in_sizes, int n_in,
                              void* d_out, int out_size)
{
    (void)in_sizes; (void)n_in; (void)out_size;
    const float* img      = (const float*)d_in[0];
    const float* pe_ln1_g = (const float*)d_in[1];
    const float* pe_ln1_b = (const float*)d_in[2];
    const float* pe_w     = (const float*)d_in[3];
    const float* pe_b     = (const float*)d_in[4];
    const float* pe_ln2_g = (const float*)d_in[5];
    const float* pe_ln2_b = (const float*)d_in[6];
    const float* pos_emb  = (const float*)d_in[7];
    const float* cls_tok  = (const float*)d_in[8];
    const float* ln_w     = (const float*)d_in[9];
    const float* ln_b     = (const float*)d_in[10];
    const float* in_w     = (const float*)d_in[11];
    const float* conv_w   = (const float*)d_in[12];
    const float* conv_b   = (const float*)d_in[13];
    const float* xproj_w  = (const float*)d_in[14];
    const float* dtproj_w = (const float*)d_in[15];
    const float* dtproj_b = (const float*)d_in[16];
    const float* A_log    = (const float*)d_in[17];
    const float* Dp       = (const float*)d_in[18];
    const float* out_w    = (const float*)d_in[19];
    const float* normf_w  = (const float*)d_in[20];
    const float* normf_b  = (const float*)d_in[21];
    const float* head_w   = (const float*)d_in[22];
    const float* head_b   = (const float*)d_in[23];
    float* out = (float*)d_out;

    __nv_bfloat16 *p_xpb, *p_xnb, *p_ub, *p_yb, *p_wpe, *p_win, *p_wxp, *p_wout;
    float *p_xe, *p_xz, *p_res, *p_dbc;
    cudaGetSymbolAddress((void**)&p_xpb, g_xpb);
    cudaGetSymbolAddress((void**)&p_xnb, g_xnb);
    cudaGetSymbolAddress((void**)&p_ub , g_ub );
    cudaGetSymbolAddress((void**)&p_yb , g_yb );
    cudaGetSymbolAddress((void**)&p_wpe, w_pe );
    cudaGetSymbolAddress((void**)&p_win, w_in );
    cudaGetSymbolAddress((void**)&p_wxp, w_xp );
    cudaGetSymbolAddress((void**)&p_wout, w_out);
    cudaGetSymbolAddress((void**)&p_xe , g_xe );
    cudaGetSymbolAddress((void**)&p_xz , g_xz );
    cudaGetSymbolAddress((void**)&p_res, g_res);
    cudaGetSymbolAddress((void**)&p_dbc, g_dbc);

    const int SMEM_BIG   = 2 * (128*128 + 64*128*2);           // 65536 (<128,128>)
    const int SMEM_SMALL = 2 * (64*128 + 64*64*2);             // 32768 (<64,64>)
    const int SMEM_ADD   = SMEM_SMALL + 64*64*4;               // 49152 (<64,64> + C tile)
    const int SMEM_XP    = 2 * (32*128 + 64*64*2);             // 24576 (<32,64>)
    cudaFuncSetAttribute((const void*)mmabf16<128,128,64,32,false>,
                         cudaFuncAttributeMaxDynamicSharedMemorySize, SMEM_BIG);
    cudaFuncSetAttribute((const void*)mmabf16<64,64,32,32,false>,
                         cudaFuncAttributeMaxDynamicSharedMemorySize, SMEM_SMALL);
    cudaFuncSetAttribute((const void*)mmabf16<32,64,16,32,false>,
                         cudaFuncAttributeMaxDynamicSharedMemorySize, SMEM_XP);
    cudaFuncSetAttribute((const void*)mmabf16<64,64,32,32,true>,
                         cudaFuncAttributeMaxDynamicSharedMemorySize, SMEM_ADD);

    // weight conversion (single kernel)
    {
        int total4 = (PD*DIMM + NL*DIMM*2*DI + NL*DI*48 + NL*DI*DIMM) / 4;
        cvt_all<<<(total4 + 255)/256, 256>>>(pe_w, in_w, xproj_w, out_w,
                                             p_wpe, p_win, p_wxp, p_wout);
    }

    // patch embed
    patchify_ln<<<PROWS, 256>>>(img, pe_ln1_g, pe_ln1_b);
    {   // g_xe = g_xpb @ w_pe  (3136 x 256 x 768)
        dim3 grid(DIMM / 64, PROWS / 64);
        mmabf16<64,64,32,32,false><<<grid, 128, SMEM_SMALL>>>(p_xpb, p_wpe, p_xe,
                                                              PROWS, DIMM, PD);
    }
    pe2_posemb<<<(PROWS + BB + 7) / 8, 256>>>(pe_b, pe_ln2_g, pe_ln2_b, pos_emb, cls_tok);

    for (int i = 0; i < 8; i++) {
        ln_res<<<NROWS / 8, 256>>>(ln_w + i * DIMM, ln_b + i * DIMM);
        {   // g_xz = g_xnb @ w_in[i]  (3152 x 1024 x 256) -> fp32
            dim3 grid((2 * DI) / 128, (NROWS + 127) / 128);
            mmabf16<128,128,64,32,false><<<grid, 256, SMEM_BIG>>>(
                p_xnb, p_win + (size_t)i * DIMM * 2 * DI, p_xz,
                NROWS, 2 * DI, DIMM);
        }
        conv_silu<<<(NROWS * DI / 4 + 255) / 256, 256>>>(conv_w + (size_t)i * DI * 4, conv_b + i * DI);
        {   // g_dbc = g_ub @ w_xp[i]  (3152 x 48 x 512), 99 blocks / 128 thr
            dim3 grid(1, (NROWS + 31) / 32);
            mmabf16<32,64,16,32,false><<<grid, 128, SMEM_XP>>>(
                p_ub, p_wxp + (size_t)i * DI * 48, p_dbc, NROWS, 48, DI);
        }
        scan_k<<<BB * 8, 128>>>(A_log + (size_t)i * DI * DS, Dp + i * DI,
                                dtproj_w + (size_t)i * 16 * DI, dtproj_b + i * DI);
        {   // g_res += g_yb @ w_out[i]  (3152 x 256 x 512), fused residual (prefetched)
            dim3 grid(DIMM / 64, (NROWS + 63) / 64);
            mmabf16<64,64,32,32,true><<<grid, 128, SMEM_ADD>>>(
                p_yb, p_wout + (size_t)i * DI * DIMM, p_res, NROWS, DIMM, DI);
        }
    }

    lnhead_k<<<BB, 256>>>(normf_w, normf_b, head_w, head_b, out);
}